// round 3
// baseline (speedup 1.0000x reference)
#include <cuda_runtime.h>

// x: (B=8, ns=4, D=512, nc=64) fp32
// out: concat(map_hidden, map_mask), each (B, D, 4, 64, 65) fp32.
// For rel in 0..3, base=1<<rel:
//   out[b,d,rel,i,j] = max(x[b,rel,d, i .. i+k-1]) where k=(j-i)/base,
//   valid when i%base==0, (j-i)%base==0, i<j<64 (note: window is k
//   elements, NOT k*base — matches the reference's stride-1 sliding max).
// Mask = 1.0 at the same positions.
//
// Pure store-bound kernel (~545 MB out). Shared running-max table is packed:
// a rel-r row only needs 64>>r entries (k <= 64/base).

#define B_DIM 8
#define D_DIM 512
#define NC 64
#define NJ 65
#define REGION (4 * NC * NJ)        // 16640 floats per half per (b,d)

// Packed S layout: rel0 64x64, rel1 32x32, rel2 16x16, rel3 8x8
#define SB0 0
#define SB1 4096
#define SB2 5120
#define SB3 5376
#define S_WORDS 5440                // 21.25 KB

__global__ __launch_bounds__(256, 1)
void prop3d_kernel(const float* __restrict__ x, float* __restrict__ out,
                   long half_elems) {
    __shared__ float xs[4][NC];     // input slice (1 KB)
    __shared__ float Sp[S_WORDS];   // packed running-max table

    const int bd  = blockIdx.x;     // b*512 + d
    const int b   = bd >> 9;
    const int d   = bd & 511;
    const int tid = threadIdx.x;

    // ---- load x[b, rel, d, :] for rel = 0..3 (coalesced) ----
    {
        int rel = tid >> 6;
        int c   = tid & 63;
        xs[rel][c] = x[((((b << 2) + rel) * D_DIM) + d) * NC + c];
    }
    __syncthreads();

    // ---- build packed running-max rows (tid < 120 rows total) ----
    // rel0: rows 0..63 (i=r), rel1: 64..95 (i=2(r-64)),
    // rel2: 96..111 (i=4(r-96)), rel3: 112..119 (i=8(r-112))
    if (tid < 120) {
        int rel, i, base_off, width;
        if (tid < 64)       { rel = 0; i = tid;              base_off = SB0 + (i >> 0) * 64; width = 64; }
        else if (tid < 96)  { rel = 1; i = (tid - 64)  << 1; base_off = SB1 + (i >> 1) * 32; width = 32; }
        else if (tid < 112) { rel = 2; i = (tid - 96)  << 2; base_off = SB2 + (i >> 2) * 16; width = 16; }
        else                { rel = 3; i = (tid - 112) << 3; base_off = SB3 + (i >> 3) * 8;  width = 8;  }
        int emax = (i + width < NC) ? (i + width) : NC;   // entries e = i..emax-1
        float m = xs[rel][i];
        Sp[base_off] = m;
        for (int e = i + 1; e < emax; e++) {
            m = fmaxf(m, xs[rel][e]);
            Sp[base_off + (e - i)] = m;
        }
    }
    __syncthreads();

    // ---- write loop: 4 rel blocks x 1040 float4 chunks each ----
    float* __restrict__ hid = out + (long)bd * REGION;
    float* __restrict__ msk = hid + half_elems;

    const int sbase[4] = {SB0, SB1, SB2, SB3};

    #pragma unroll
    for (int rel = 0; rel < 4; rel++) {
        const int bm   = (1 << rel) - 1;   // base-1
        const int ws   = 6 - rel;          // log2(row width)
        const int sb   = sbase[rel];
        const int blk  = rel * 4160;       // float offset of this rel block

        for (int qq = tid; qq < 1040; qq += 256) {
            int er = qq << 2;              // element offset within rel block
            int i  = er / 65;              // compiler -> umulhi
            int j  = er - i * 65;

            float4 h, m;
            float* hp = reinterpret_cast<float*>(&h);
            float* mp = reinterpret_cast<float*>(&m);

            #pragma unroll
            for (int l = 0; l < 4; l++) {
                int jj = j + l;
                int ii = i;
                if (jj >= NJ) { jj -= NJ; ii += 1; }       // one row wrap max
                int diff = jj - ii;
                bool hit = (diff > 0) & (jj < NC) & (((ii | diff) & bm) == 0);
                float hv = 0.0f, mv = 0.0f;
                if (hit) {
                    hv = Sp[sb + ((ii >> rel) << ws) + (diff >> rel) - 1];
                    mv = 1.0f;
                }
                hp[l] = hv;
                mp[l] = mv;
            }

            int off = blk + er;
            __stwt(reinterpret_cast<float4*>(hid + off), h);
            __stwt(reinterpret_cast<float4*>(msk + off), m);
        }
    }
}

extern "C" void kernel_launch(void* const* d_in, const int* in_sizes, int n_in,
                              void* d_out, int out_size) {
    const float* x = (const float*)d_in[0];
    float* out = (float*)d_out;
    long half = (long)out_size / 2;     // map_hidden elements; map_mask follows

    prop3d_kernel<<<B_DIM * D_DIM, 256>>>(x, out, half);
}

// round 4
// speedup vs baseline: 1.0410x; 1.0410x over previous
#include <cuda_runtime.h>

// x: (B=8, ns=4, D=512, nc=64) fp32
// out: concat(map_hidden, map_mask), each (B, D, 4, 64, 65) fp32.
// For rel in 0..3, base=1<<rel:
//   out[b,d,rel,i,j] = max(x[b,rel,d, i .. i+k-1]) where k=(j-i)/base,
//   valid when i%base==0, (j-i)%base==0, i<j<64. Mask = 1.0 at hits.
//
// Pure store-bound kernel (~545 MB out) — pinned at the HBM write wall.
// Packed shared running-max table: rel-r rows need only 64>>r entries.

#define B_DIM 8
#define D_DIM 512
#define NC 64
#define NJ 65
#define REGION (4 * NC * NJ)        // 16640 floats per half per (b,d)

// Packed S layout: rel0 64x64, rel1 32x32, rel2 16x16, rel3 8x8
#define SB0 0
#define SB1 4096
#define SB2 5120
#define SB3 5376
#define S_WORDS 5440                // 21.25 KB

__global__ __launch_bounds__(256, 1)
void prop3d_kernel(const float* __restrict__ x, float* __restrict__ out,
                   long half_elems) {
    __shared__ float xs[4][NC];     // input slice (1 KB)
    __shared__ float Sp[S_WORDS];   // packed running-max table

    const int bd  = blockIdx.x;     // b*512 + d
    const int b   = bd >> 9;
    const int d   = bd & 511;
    const int tid = threadIdx.x;

    // ---- load x[b, rel, d, :] for rel = 0..3 (coalesced) ----
    {
        int rel = tid >> 6;
        int c   = tid & 63;
        xs[rel][c] = x[((((b << 2) + rel) * D_DIM) + d) * NC + c];
    }
    __syncthreads();

    // ---- build packed running-max rows (120 rows total) ----
    if (tid < 120) {
        int rel, i, base_off, width;
        if (tid < 64)       { rel = 0; i = tid;              base_off = SB0 + (i >> 0) * 64; width = 64; }
        else if (tid < 96)  { rel = 1; i = (tid - 64)  << 1; base_off = SB1 + (i >> 1) * 32; width = 32; }
        else if (tid < 112) { rel = 2; i = (tid - 96)  << 2; base_off = SB2 + (i >> 2) * 16; width = 16; }
        else                { rel = 3; i = (tid - 112) << 3; base_off = SB3 + (i >> 3) * 8;  width = 8;  }
        int emax = (i + width < NC) ? (i + width) : NC;
        float m = xs[rel][i];
        Sp[base_off] = m;
        for (int e = i + 1; e < emax; e++) {
            m = fmaxf(m, xs[rel][e]);
            Sp[base_off + (e - i)] = m;
        }
    }
    __syncthreads();

    // ---- write loop: 4 rel blocks x 1040 float4 chunks each ----
    float* __restrict__ hid = out + (long)bd * REGION;
    float* __restrict__ msk = hid + half_elems;

    const int sbase[4] = {SB0, SB1, SB2, SB3};

    #pragma unroll
    for (int rel = 0; rel < 4; rel++) {
        const int bm   = (1 << rel) - 1;   // base-1
        const int ws   = 6 - rel;          // log2(row width)
        const int sb   = sbase[rel];
        const int blk  = rel * 4160;       // float offset of this rel block

        for (int qq = tid; qq < 1040; qq += 256) {
            int er = qq << 2;              // element offset within rel block
            int i  = er / 65;              // strength-reduced by compiler
            int j  = er - i * 65;

            float4 h, m;
            float* hp = reinterpret_cast<float*>(&h);
            float* mp = reinterpret_cast<float*>(&m);

            #pragma unroll
            for (int l = 0; l < 4; l++) {
                int jj = j + l;
                int ii = i;
                if (jj >= NJ) { jj -= NJ; ii += 1; }       // one row wrap max
                int diff = jj - ii;
                bool hit = (diff > 0) & (jj < NC) & (((ii | diff) & bm) == 0);
                float hv = 0.0f, mv = 0.0f;
                if (hit) {
                    hv = Sp[sb + ((ii >> rel) << ws) + (diff >> rel) - 1];
                    mv = 1.0f;
                }
                hp[l] = hv;
                mp[l] = mv;
            }

            int off = blk + er;
            __stcs(reinterpret_cast<float4*>(hid + off), h);   // streaming, evict-first
            __stcs(reinterpret_cast<float4*>(msk + off), m);
        }
    }
}

extern "C" void kernel_launch(void* const* d_in, const int* in_sizes, int n_in,
                              void* d_out, int out_size) {
    const float* x = (const float*)d_in[0];
    float* out = (float*)d_out;
    long half = (long)out_size / 2;     // map_hidden elements; map_mask follows

    prop3d_kernel<<<B_DIM * D_DIM, 256>>>(x, out, half);
}

// round 5
// speedup vs baseline: 1.1033x; 1.0599x over previous
#include <cuda_runtime.h>

// x: (B=8, ns=4, D=512, nc=64) fp32
// out: concat(map_hidden, map_mask), each (B, D, 4, 64, 65) fp32.
// For rel in 0..3, base=1<<rel:
//   out[b,d,rel,i,j] = max(x[b,rel,d, i .. i+k-1]) where k=(j-i)/base,
//   valid when i%base==0, (j-i)%base==0, i<j<64. Mask = 1.0 at hits.
//
// Pure store-bound (~545 MB out). 2 CTAs per (b,d): parity 0 covers rel
// blocks {0,1}, parity 1 covers {2,3}. Finer grid granularity smooths
// wave tails; each CTA builds only the running-max rows it needs.

#define B_DIM 8
#define D_DIM 512
#define NC 64
#define NJ 65
#define REGION (4 * NC * NJ)        // 16640 floats per half per (b,d)

#define S_WORDS 5120                // h=0: rel0 64x64 + rel1 32x32 (20 KB)

__global__ __launch_bounds__(256, 1)
void prop3d_kernel(const float* __restrict__ x, float* __restrict__ out,
                   long half_elems) {
    __shared__ float xs[2][NC];     // 2 input rows for this CTA's rels
    __shared__ float Sp[S_WORDS];   // packed running-max table

    const int bid = blockIdx.x;
    const int bd  = bid >> 1;       // b*512 + d
    const int h   = bid & 1;        // 0 -> rels {0,1}, 1 -> rels {2,3}
    const int b   = bd >> 9;
    const int d   = bd & 511;
    const int tid = threadIdx.x;

    // ---- load x[b, 2h + rl, d, :] for rl = 0,1 (coalesced, 128 threads) ----
    if (tid < 128) {
        int rl = tid >> 6;
        int c  = tid & 63;
        xs[rl][c] = x[((((b << 2) + (h * 2 + rl)) * D_DIM) + d) * NC + c];
    }
    __syncthreads();

    // ---- build packed running-max rows for this CTA's two rels ----
    // h=0: rel0 rows 0..63 (i=r)         at Sp[i*64], width 64
    //      rel1 rows 64..95 (i=2(r-64))  at Sp[4096 + (i>>1)*32], width 32
    // h=1: rel2 rows 0..15 (i=4r)        at Sp[(i>>2)*16], width 16
    //      rel3 rows 16..23 (i=8(r-16))  at Sp[256 + (i>>3)*8], width 8
    {
        int rl = -1, i = 0, base_off = 0, width = 0;
        if (h == 0) {
            if (tid < 64)      { rl = 0; i = tid;             base_off = i * 64;                width = 64; }
            else if (tid < 96) { rl = 1; i = (tid - 64) << 1; base_off = 4096 + (i >> 1) * 32;  width = 32; }
        } else {
            if (tid < 16)      { rl = 0; i = tid << 2;        base_off = (i >> 2) * 16;         width = 16; }
            else if (tid < 24) { rl = 1; i = (tid - 16) << 3; base_off = 256 + (i >> 3) * 8;    width = 8;  }
        }
        if (rl >= 0) {
            int emax = (i + width < NC) ? (i + width) : NC;
            float m = xs[rl][i];
            Sp[base_off] = m;
            for (int e = i + 1; e < emax; e++) {
                m = fmaxf(m, xs[rl][e]);
                Sp[base_off + (e - i)] = m;
            }
        }
    }
    __syncthreads();

    // ---- write loop: 2 rel blocks x 1040 float4 chunks each ----
    float* __restrict__ hid = out + (long)bd * REGION;
    float* __restrict__ msk = hid + half_elems;

    const int sb1 = (h == 0) ? 4096 : 256;   // second rel's table base

    #pragma unroll
    for (int r2 = 0; r2 < 2; r2++) {
        const int rel = h * 2 + r2;
        const int bm  = (1 << rel) - 1;      // base-1
        const int ws  = 6 - rel;             // log2(row width)
        const int sb  = r2 ? sb1 : 0;
        const int blk = rel * 4160;          // float offset of this rel block

        for (int qq = tid; qq < 1040; qq += 256) {
            int er = qq << 2;                // element offset within rel block
            int i  = er / 65;                // const-divisor -> mulhi
            int j  = er - i * 65;

            float4 hv4, mv4;
            float* hp = reinterpret_cast<float*>(&hv4);
            float* mp = reinterpret_cast<float*>(&mv4);

            #pragma unroll
            for (int l = 0; l < 4; l++) {
                int jj = j + l;
                int ii = i;
                if (jj >= NJ) { jj -= NJ; ii += 1; }       // one row wrap max
                int diff = jj - ii;
                bool hit = (diff > 0) & (jj < NC) & (((ii | diff) & bm) == 0);
                float hv = 0.0f, mv = 0.0f;
                if (hit) {
                    hv = Sp[sb + ((ii >> rel) << ws) + (diff >> rel) - 1];
                    mv = 1.0f;
                }
                hp[l] = hv;
                mp[l] = mv;
            }

            int off = blk + er;
            *reinterpret_cast<float4*>(hid + off) = hv4;
            *reinterpret_cast<float4*>(msk + off) = mv4;
        }
    }
}

extern "C" void kernel_launch(void* const* d_in, const int* in_sizes, int n_in,
                              void* d_out, int out_size) {
    const float* x = (const float*)d_in[0];
    float* out = (float*)d_out;
    long half = (long)out_size / 2;     // map_hidden elements; map_mask follows

    prop3d_kernel<<<B_DIM * D_DIM * 2, 256>>>(x, out, half);
}

// round 6
// speedup vs baseline: 1.1278x; 1.0222x over previous
#include <cuda_runtime.h>

// x: (B=8, ns=4, D=512, nc=64) fp32
// out: concat(map_hidden, map_mask), each (B, D, 4, 64, 65) fp32.
// For rel in 0..3, base=1<<rel:
//   out[b,d,rel,i,j] = max(x[b,rel,d, i .. i+k-1]) where k=(j-i)/base,
//   valid when i%base==0, (j-i)%base==0, i<j<64. Mask = 1.0 at hits.
//
// Pure store-bound (~545 MB out). 4 CTAs per (b,d) — one per rel — with
// the write loop templated on REL so all masks/shifts are compile-time.

#define B_DIM 8
#define D_DIM 512
#define NC 64
#define NJ 65
#define REGION (4 * NC * NJ)        // 16640 floats per half per (b,d)
#define RELBLK (NC * NJ)            // 4160 floats per rel block

template<int REL>
__device__ __forceinline__ void prop3d_rel(
    const float* __restrict__ xrow,     // x[b, REL, d, :] (global)
    float* __restrict__ hid,            // out + bd*REGION
    float* __restrict__ msk,            // hid + half
    float* __restrict__ Sp,             // shared, >= (64>>REL)^2 words
    float* __restrict__ xsh,            // shared, 64 words
    int tid)
{
    constexpr int W    = NC >> REL;     // row width / row count
    constexpr int BM   = (1 << REL) - 1;
    constexpr int BLK  = REL * RELBLK;

    // ---- stage input row ----
    if (tid < NC) xsh[tid] = xrow[tid];
    __syncthreads();

    // ---- build running-max rows: i = r<<REL, entries k-1 = 0..emax ----
    if (tid < W) {
        int i = tid << REL;
        int base_off = tid * W;
        int emax = (i + W < NC) ? (i + W) : NC;
        float m = xsh[i];
        Sp[base_off] = m;
        #pragma unroll 4
        for (int e = i + 1; e < emax; e++) {
            m = fmaxf(m, xsh[e]);
            Sp[base_off + (e - i)] = m;
        }
    }
    __syncthreads();

    // ---- write loop: 1040 float4 chunks over this rel block ----
    for (int qq = tid; qq < RELBLK / 4; qq += 256) {
        int er = qq << 2;               // element offset within rel block
        int i  = er / 65;               // const divisor -> mulhi
        int j  = er - i * 65;

        float4 hv4, mv4;
        float* hp = reinterpret_cast<float*>(&hv4);
        float* mp = reinterpret_cast<float*>(&mv4);

        #pragma unroll
        for (int l = 0; l < 4; l++) {
            int jj = j + l;
            int ii = i;
            if (jj >= NJ) { jj -= NJ; ii += 1; }       // one row wrap max
            int diff = jj - ii;
            bool hit;
            if (REL == 0)
                hit = (diff > 0) & (jj < NC);
            else
                hit = (diff > 0) & (jj < NC) & (((ii | diff) & BM) == 0);
            float hv = 0.0f, mv = 0.0f;
            if (hit) {
                hv = Sp[(ii >> REL) * W + (diff >> REL) - 1];
                mv = 1.0f;
            }
            hp[l] = hv;
            mp[l] = mv;
        }

        int off = BLK + er;
        *reinterpret_cast<float4*>(hid + off) = hv4;
        *reinterpret_cast<float4*>(msk + off) = mv4;
    }
}

__global__ __launch_bounds__(256, 1)
void prop3d_kernel(const float* __restrict__ x, float* __restrict__ out,
                   long half_elems) {
    __shared__ float xsh[NC];
    __shared__ float Sp[4096];          // max table: rel0 64x64 (16 KB)

    const int bid = blockIdx.x;
    const int bd  = bid >> 2;           // b*512 + d
    const int rel = bid & 3;
    const int b   = bd >> 9;
    const int d   = bd & 511;
    const int tid = threadIdx.x;

    const float* xrow = x + ((((long)(b << 2) + rel) * D_DIM) + d) * NC;
    float* hid = out + (long)bd * REGION;
    float* msk = hid + half_elems;

    switch (rel) {
        case 0: prop3d_rel<0>(xrow, hid, msk, Sp, xsh, tid); break;
        case 1: prop3d_rel<1>(xrow, hid, msk, Sp, xsh, tid); break;
        case 2: prop3d_rel<2>(xrow, hid, msk, Sp, xsh, tid); break;
        default: prop3d_rel<3>(xrow, hid, msk, Sp, xsh, tid); break;
    }
}

extern "C" void kernel_launch(void* const* d_in, const int* in_sizes, int n_in,
                              void* d_out, int out_size) {
    const float* x = (const float*)d_in[0];
    float* out = (float*)d_out;
    long half = (long)out_size / 2;     // map_hidden elements; map_mask follows

    prop3d_kernel<<<B_DIM * D_DIM * 4, 256>>>(x, out, half);
}